// round 3
// baseline (speedup 1.0000x reference)
#include <cuda_runtime.h>

// ---------------------------------------------------------------------------
// SphericalExpansion: out[i, comp(16), q*8+n(16)] = sum over pairs p with
// centers[p]==i of  Y_comp(u_p) * W[q, species[neighbors[p]]] * radial_n(r_p)
//
// Strategy: bucket pairs by center (1 int atomic/pair), then one warp per atom
// accumulates its pairs' rank-1 outer products via shared-memory staging.
// ---------------------------------------------------------------------------

constexpr int MAX_ATOMS = 20000;
constexpr int CAP       = 128;      // max pairs per atom bucket (mean ~25)
constexpr float R_CUT_F = 5.0f;
constexpr float PI_F    = 3.14159265358979323846f;

__device__ int g_count[MAX_ATOMS];
__device__ int g_bucket[MAX_ATOMS * CAP];

__global__ void k_zero(int n) {
    int i = blockIdx.x * blockDim.x + threadIdx.x;
    if (i < n) g_count[i] = 0;
}

__global__ void k_fill(const int* __restrict__ centers, int P) {
    int p = blockIdx.x * blockDim.x + threadIdx.x;
    if (p >= P) return;
    int c = centers[p];
    int slot = atomicAdd(&g_count[c], 1);
    if (slot < CAP) g_bucket[c * CAP + slot] = p;
}

__global__ __launch_bounds__(256) void k_acc(
    const float* __restrict__ pos,        // [nAtoms, 3]
    const float* __restrict__ W,          // [2, 4] row-major
    const int*   __restrict__ neighbors,  // [P]
    const int*   __restrict__ species,    // [nAtoms]
    float*       __restrict__ out,        // [nAtoms, 16, 16]
    int nAtoms)
{
    // Padded rows (17) -> conflict-free lane-major writes, broadcast reads.
    __shared__ float sY[8][32][17];
    __shared__ float sF[8][32][17];

    const int w    = threadIdx.x >> 5;
    const int lane = threadIdx.x & 31;
    const int atom = blockIdx.x * 8 + w;
    if (atom >= nAtoms) return;

    int cnt = g_count[atom];
    if (cnt > CAP) cnt = CAP;

    const float cx = pos[3 * atom + 0];
    const float cy = pos[3 * atom + 1];
    const float cz = pos[3 * atom + 2];

    float acc[8];
#pragma unroll
    for (int j = 0; j < 8; j++) acc[j] = 0.0f;

    // lane -> owned output elements e = lane*8 + j;  comp = e>>4, col = e&15.
    // comp is constant per lane (= lane>>1); cols are contiguous 8-run.
    const int cidx  = lane >> 1;
    const int fbase = (lane & 1) << 3;

    for (int base = 0; base < cnt; base += 32) {
        const int k = base + lane;
        float Y[16], F[16];
        if (k < cnt) {
            const int p  = g_bucket[atom * CAP + k];
            const int nb = neighbors[p];
            const float dx = pos[3 * nb + 0] - cx;
            const float dy = pos[3 * nb + 1] - cy;
            const float dz = pos[3 * nb + 2] - cz;
            const float r2   = dx * dx + dy * dy + dz * dz + 1e-12f;
            const float r    = sqrtf(r2);
            const float rinv = 1.0f / r;
            const float x = dx * rinv, y = dy * rinv, z = dz * rinv;
            const float x2 = x * x, y2 = y * y, z2 = z * z;

            Y[0]  = 0.28209479177387814f;
            Y[1]  = 0.4886025119029199f * y;
            Y[2]  = 0.4886025119029199f * z;
            Y[3]  = 0.4886025119029199f * x;
            Y[4]  = 1.0925484305920792f * x * y;
            Y[5]  = 1.0925484305920792f * y * z;
            Y[6]  = 0.31539156525252005f * (3.0f * z2 - 1.0f);
            Y[7]  = 1.0925484305920792f * x * z;
            Y[8]  = 0.5462742152960396f * (x2 - y2);
            Y[9]  = 0.5900435899266435f * y * (3.0f * x2 - y2);
            Y[10] = 2.890611442640554f  * x * y * z;
            Y[11] = 0.4570457994644658f * y * (5.0f * z2 - 1.0f);
            Y[12] = 0.3731763325901154f * z * (5.0f * z2 - 3.0f);
            Y[13] = 0.4570457994644658f * x * (5.0f * z2 - 1.0f);
            Y[14] = 1.445305721320277f  * z * (x2 - y2);
            Y[15] = 0.5900435899266435f * x * (x2 - 3.0f * y2);

            const float fc = (r < R_CUT_F)
                ? 0.5f * (__cosf(PI_F * r * (1.0f / R_CUT_F)) + 1.0f)
                : 0.0f;

            const int   s  = species[nb];
            const float w0 = W[s];
            const float w1 = W[4 + s];

            const float sigma_inv = 8.0f / R_CUT_F;  // 1/sigma = 1.6
#pragma unroll
            for (int n = 0; n < 8; n++) {
                const float cn  = R_CUT_F * (float)n * (1.0f / 7.0f);
                const float t   = (r - cn) * sigma_inv;
                const float rad = __expf(-0.5f * t * t) * fc;
                F[n]     = w0 * rad;
                F[8 + n] = w1 * rad;
            }
        } else {
#pragma unroll
            for (int j = 0; j < 16; j++) { Y[j] = 0.0f; F[j] = 0.0f; }
        }

#pragma unroll
        for (int j = 0; j < 16; j++) {
            sY[w][lane][j] = Y[j];
            sF[w][lane][j] = F[j];
        }
        __syncwarp();

#pragma unroll
        for (int p = 0; p < 32; p++) {
            const float yv = sY[w][p][cidx];
#pragma unroll
            for (int j = 0; j < 8; j++)
                acc[j] += yv * sF[w][p][fbase + j];
        }
        __syncwarp();
    }

    // Each lane writes its 8 contiguous floats: two float4 stores.
    float4* o = (float4*)(out + (size_t)atom * 256 + lane * 8);
    o[0] = make_float4(acc[0], acc[1], acc[2], acc[3]);
    o[1] = make_float4(acc[4], acc[5], acc[6], acc[7]);
}

extern "C" void kernel_launch(void* const* d_in, const int* in_sizes, int n_in,
                              void* d_out, int out_size) {
    const float* pos       = (const float*)d_in[0];
    const float* W         = (const float*)d_in[1];
    const int*   centers   = (const int*)d_in[2];
    const int*   neighbors = (const int*)d_in[3];
    const int*   species   = (const int*)d_in[4];
    float*       out       = (float*)d_out;

    const int P      = in_sizes[2];
    const int nAtoms = in_sizes[4];

    k_zero<<<(nAtoms + 255) / 256, 256>>>(nAtoms);
    k_fill<<<(P + 255) / 256, 256>>>(centers, P);
    k_acc<<<(nAtoms + 7) / 8, 256>>>(pos, W, neighbors, species, out, nAtoms);
}

// round 8
// speedup vs baseline: 1.1881x; 1.1881x over previous
#include <cuda_runtime.h>

// ---------------------------------------------------------------------------
// SphericalExpansion:
//  - k_fill filters r >= R_CUT pairs (fc==0 => exact zero contribution) and
//    stores (dx,dy,dz,species) payload per bucket slot.
//  - k_acc: one warp per atom; stride-20 smem rows (LDS.128 reads), 8-wide
//    dynamic sub-tiles, 2-expf radial recurrence with runtime-accurate KN.
//    k_acc self-resets g_count for the next call (zero-init at load).
// ---------------------------------------------------------------------------

constexpr int MAX_ATOMS = 20000;
constexpr int CAP       = 96;       // mean filtered count ~16; huge margin
constexpr float R_CUT_F = 5.0f;

__device__ int    g_count[MAX_ATOMS];        // zero-initialized at module load
__device__ float4 g_vec[MAX_ATOMS * CAP];    // (dx,dy,dz, species-as-float)

__global__ void k_fill(const float* __restrict__ pos,
                       const int*   __restrict__ centers,
                       const int*   __restrict__ neighbors,
                       const int*   __restrict__ species, int P)
{
    int p = blockIdx.x * blockDim.x + threadIdx.x;
    if (p >= P) return;
    const int c  = centers[p];
    const int nb = neighbors[p];
    const float dx = __ldg(&pos[3 * nb + 0]) - __ldg(&pos[3 * c + 0]);
    const float dy = __ldg(&pos[3 * nb + 1]) - __ldg(&pos[3 * c + 1]);
    const float dz = __ldg(&pos[3 * nb + 2]) - __ldg(&pos[3 * c + 2]);
    const float r2 = dx * dx + dy * dy + dz * dz;
    if (r2 >= R_CUT_F * R_CUT_F) return;      // cosine cutoff -> exact zero
    const int slot = atomicAdd(&g_count[c], 1);
    if (slot < CAP) {
        const int s = __ldg(&species[nb]);
        g_vec[c * CAP + slot] = make_float4(dx, dy, dz, __int_as_float(s));
    }
}

__global__ __launch_bounds__(256) void k_acc(
    const float* __restrict__ W,     // [2,4] row-major
    float*       __restrict__ out,   // [nAtoms, 16, 16]
    int nAtoms)
{
    // stride 20 floats: 16B-aligned rows, conflict-free lane-major writes,
    // broadcast reads (all lanes of a warp read the same row p).
    __shared__ __align__(16) float sY[8][32][20];
    __shared__ __align__(16) float sF[8][32][20];
    __shared__ float sW[8];

    if (threadIdx.x < 8) sW[threadIdx.x] = W[threadIdx.x];
    __syncthreads();

    const int w    = threadIdx.x >> 5;
    const int lane = threadIdx.x & 31;
    const int atom = blockIdx.x * 8 + w;
    if (atom >= nAtoms) return;

    int cnt = g_count[atom];
    if (lane == 0) g_count[atom] = 0;   // self-reset for next kernel_launch
    if (cnt > CAP) cnt = CAP;

    float acc[8];
#pragma unroll
    for (int j = 0; j < 8; j++) acc[j] = 0.0f;

    // lane owns out elements e = lane*8+j: comp = lane>>1 (const), col = (lane&1)*8+j
    const int cidx  = lane >> 1;
    const int fbase = (lane & 1) << 3;

    // KN[n] = exp(-(32/49) n^2), computed accurately once per thread.
    float KN[8];
#pragma unroll
    for (int n = 0; n < 8; n++)
        KN[n] = expf(-0.6530612244897959f * (float)(n * n));

    for (int base = 0; base < cnt; base += 32) {
        const int k = base + lane;
        float Y[16], F[16];
        if (k < cnt) {
            const float4 v = __ldg(&g_vec[atom * CAP + k]);
            const float r2   = v.x * v.x + v.y * v.y + v.z * v.z + 1e-12f;
            const float rinv = rsqrtf(r2);
            const float r    = r2 * rinv;
            const float x = v.x * rinv, y = v.y * rinv, z = v.z * rinv;
            const float x2 = x * x, y2 = y * y, z2 = z * z;

            Y[0]  = 0.28209479177387814f;
            Y[1]  = 0.4886025119029199f * y;
            Y[2]  = 0.4886025119029199f * z;
            Y[3]  = 0.4886025119029199f * x;
            Y[4]  = 1.0925484305920792f * x * y;
            Y[5]  = 1.0925484305920792f * y * z;
            Y[6]  = 0.31539156525252005f * (3.0f * z2 - 1.0f);
            Y[7]  = 1.0925484305920792f * x * z;
            Y[8]  = 0.5462742152960396f * (x2 - y2);
            Y[9]  = 0.5900435899266435f * y * (3.0f * x2 - y2);
            Y[10] = 2.890611442640554f  * x * y * z;
            Y[11] = 0.4570457994644658f * y * (5.0f * z2 - 1.0f);
            Y[12] = 0.3731763325901154f * z * (5.0f * z2 - 3.0f);
            Y[13] = 0.4570457994644658f * x * (5.0f * z2 - 1.0f);
            Y[14] = 1.445305721320277f  * z * (x2 - y2);
            Y[15] = 0.5900435899266435f * x * (x2 - 3.0f * y2);

            // r < R_CUT guaranteed by k_fill filter
            const float fc = 0.5f * (__cosf(0.6283185307179586f * r) + 1.0f);

            const int   s  = __float_as_int(v.w);
            const float w0 = sW[s];
            const float w1 = sW[4 + s];

            // radial_n = G * E^n * KN[n]:  exponent -1.28(r-cn)^2 split as
            // -1.28 r^2 + 1.8285714 r n - (32/49) n^2,  cn = 5n/7, sigma=5/8.
            const float G  = __expf(-1.28f * r * r);
            const float E  = __expf(1.8285714285714286f * r);
            const float b0 = G * fc * w0;
            const float b1 = G * fc * w1;
            float e = 1.0f;
#pragma unroll
            for (int n = 0; n < 8; n++) {
                const float rad = e * KN[n];
                F[n]     = b0 * rad;
                F[8 + n] = b1 * rad;
                e *= E;
            }
        } else {
#pragma unroll
            for (int j = 0; j < 16; j++) { Y[j] = 0.0f; F[j] = 0.0f; }
        }

#pragma unroll
        for (int j = 0; j < 4; j++) {
            *(float4*)&sY[w][lane][4 * j] = make_float4(Y[4*j], Y[4*j+1], Y[4*j+2], Y[4*j+3]);
            *(float4*)&sF[w][lane][4 * j] = make_float4(F[4*j], F[4*j+1], F[4*j+2], F[4*j+3]);
        }
        __syncwarp();

        int m = cnt - base;
        if (m > 32) m = 32;
        for (int p0 = 0; p0 < m; p0 += 8) {
#pragma unroll
            for (int pp = 0; pp < 8; pp++) {
                const int p = p0 + pp;
                const float  yv = sY[w][p][cidx];
                const float4 fa = *(const float4*)&sF[w][p][fbase];
                const float4 fb = *(const float4*)&sF[w][p][fbase + 4];
                acc[0] += yv * fa.x;  acc[1] += yv * fa.y;
                acc[2] += yv * fa.z;  acc[3] += yv * fa.w;
                acc[4] += yv * fb.x;  acc[5] += yv * fb.y;
                acc[6] += yv * fb.z;  acc[7] += yv * fb.w;
            }
        }
        __syncwarp();
    }

    float4* o = (float4*)(out + (size_t)atom * 256 + lane * 8);
    o[0] = make_float4(acc[0], acc[1], acc[2], acc[3]);
    o[1] = make_float4(acc[4], acc[5], acc[6], acc[7]);
}

extern "C" void kernel_launch(void* const* d_in, const int* in_sizes, int n_in,
                              void* d_out, int out_size) {
    const float* pos       = (const float*)d_in[0];
    const float* W         = (const float*)d_in[1];
    const int*   centers   = (const int*)d_in[2];
    const int*   neighbors = (const int*)d_in[3];
    const int*   species   = (const int*)d_in[4];
    float*       out       = (float*)d_out;

    const int P      = in_sizes[2];
    const int nAtoms = in_sizes[4];

    k_fill<<<(P + 255) / 256, 256>>>(pos, centers, neighbors, species, P);
    k_acc<<<(nAtoms + 7) / 8, 256>>>(W, out, nAtoms);
}

// round 9
// speedup vs baseline: 1.2452x; 1.0481x over previous
#include <cuda_runtime.h>

// ---------------------------------------------------------------------------
// SphericalExpansion:
//  - k_fill filters r >= R_CUT pairs (fc==0 => exact zero contribution) and
//    stores (dx,dy,dz,species) payload per bucket slot.
//  - k_acc: one warp per atom; stride-20 smem rows (LDS.128), staging bounded
//    by the live pair count, full radial recurrence from a single runtime K1.
//    k_acc self-resets g_count for the next call (zero-init at load).
// ---------------------------------------------------------------------------

constexpr int MAX_ATOMS = 20000;
constexpr int CAP       = 96;       // mean filtered count ~16; huge margin
constexpr float R_CUT_F = 5.0f;

__device__ int    g_count[MAX_ATOMS];        // zero-initialized at module load
__device__ float4 g_vec[MAX_ATOMS * CAP];    // (dx,dy,dz, species-as-float)

__global__ void k_fill(const float* __restrict__ pos,
                       const int*   __restrict__ centers,
                       const int*   __restrict__ neighbors,
                       const int*   __restrict__ species, int P)
{
    int p = blockIdx.x * blockDim.x + threadIdx.x;
    if (p >= P) return;
    const int c  = centers[p];
    const int nb = neighbors[p];
    const float dx = __ldg(&pos[3 * nb + 0]) - __ldg(&pos[3 * c + 0]);
    const float dy = __ldg(&pos[3 * nb + 1]) - __ldg(&pos[3 * c + 1]);
    const float dz = __ldg(&pos[3 * nb + 2]) - __ldg(&pos[3 * c + 2]);
    const float r2 = dx * dx + dy * dy + dz * dz;
    if (r2 >= R_CUT_F * R_CUT_F) return;      // cosine cutoff -> exact zero
    const int slot = atomicAdd(&g_count[c], 1);
    if (slot < CAP) {
        const int s = __ldg(&species[nb]);
        g_vec[c * CAP + slot] = make_float4(dx, dy, dz, __int_as_float(s));
    }
}

__global__ __launch_bounds__(256) void k_acc(
    const float* __restrict__ W,     // [2,4] row-major
    float*       __restrict__ out,   // [nAtoms, 16, 16]
    int nAtoms)
{
    // stride 20 floats: 16B-aligned rows, conflict-free lane-major writes,
    // broadcast reads (all lanes of a warp read the same row p).
    __shared__ __align__(16) float sY[8][32][20];
    __shared__ __align__(16) float sF[8][32][20];
    __shared__ float sW[8];

    if (threadIdx.x < 8) sW[threadIdx.x] = W[threadIdx.x];
    __syncthreads();

    const int w    = threadIdx.x >> 5;
    const int lane = threadIdx.x & 31;
    const int atom = blockIdx.x * 8 + w;
    if (atom >= nAtoms) return;

    int cnt = g_count[atom];
    if (lane == 0) g_count[atom] = 0;   // self-reset for next kernel_launch
    if (cnt > CAP) cnt = CAP;

    float acc[8];
#pragma unroll
    for (int j = 0; j < 8; j++) acc[j] = 0.0f;

    // lane owns out elements e = lane*8+j: comp = lane>>1 (const), col = (lane&1)*8+j
    const int cidx  = lane >> 1;
    const int fbase = (lane & 1) << 3;

    // Radial recurrence constants: rad_n = G * E^n * K1^(n^2)
    // rad_{n+1} = rad_n * u_n,  u_0 = E*K1,  u_{n+1} = u_n * K1^2.
    const float K1 = __expf(-0.6530612244897959f);   // exp(-(32/49))
    const float K2 = K1 * K1;

    for (int base = 0; base < cnt; base += 32) {
        const int k = base + lane;
        int m = cnt - base; if (m > 32) m = 32;
        const int mr = (m + 7) & ~7;   // rows the 8-unrolled reader will touch

        if (k < cnt) {
            float Y[16], F[16];
            const float4 v = __ldg(&g_vec[atom * CAP + k]);
            const float r2   = v.x * v.x + v.y * v.y + v.z * v.z + 1e-12f;
            const float rinv = rsqrtf(r2);
            const float r    = r2 * rinv;
            const float x = v.x * rinv, y = v.y * rinv, z = v.z * rinv;
            const float x2 = x * x, y2 = y * y, z2 = z * z;

            Y[0]  = 0.28209479177387814f;
            Y[1]  = 0.4886025119029199f * y;
            Y[2]  = 0.4886025119029199f * z;
            Y[3]  = 0.4886025119029199f * x;
            Y[4]  = 1.0925484305920792f * x * y;
            Y[5]  = 1.0925484305920792f * y * z;
            Y[6]  = 0.31539156525252005f * (3.0f * z2 - 1.0f);
            Y[7]  = 1.0925484305920792f * x * z;
            Y[8]  = 0.5462742152960396f * (x2 - y2);
            Y[9]  = 0.5900435899266435f * y * (3.0f * x2 - y2);
            Y[10] = 2.890611442640554f  * x * y * z;
            Y[11] = 0.4570457994644658f * y * (5.0f * z2 - 1.0f);
            Y[12] = 0.3731763325901154f * z * (5.0f * z2 - 3.0f);
            Y[13] = 0.4570457994644658f * x * (5.0f * z2 - 1.0f);
            Y[14] = 1.445305721320277f  * z * (x2 - y2);
            Y[15] = 0.5900435899266435f * x * (x2 - 3.0f * y2);

            // r < R_CUT guaranteed by k_fill filter
            const float fc = 0.5f * (__cosf(0.6283185307179586f * r) + 1.0f);

            const int   s  = __float_as_int(v.w);
            const float b0 = fc * sW[s];
            const float b1 = fc * sW[4 + s];

            float rad = __expf(-1.28f * r * r);                  // G
            float u   = __expf(1.8285714285714286f * r) * K1;    // E*K1
#pragma unroll
            for (int n = 0; n < 8; n++) {
                F[n]     = b0 * rad;
                F[8 + n] = b1 * rad;
                rad *= u;
                u   *= K2;
            }

#pragma unroll
            for (int j = 0; j < 4; j++) {
                *(float4*)&sY[w][lane][4*j] = make_float4(Y[4*j], Y[4*j+1], Y[4*j+2], Y[4*j+3]);
                *(float4*)&sF[w][lane][4*j] = make_float4(F[4*j], F[4*j+1], F[4*j+2], F[4*j+3]);
            }
        } else if (lane < mr) {
            // pad rows read by the 8-unrolled accumulator: must be finite zeros
            const float4 z4 = make_float4(0.f, 0.f, 0.f, 0.f);
#pragma unroll
            for (int j = 0; j < 4; j++) {
                *(float4*)&sY[w][lane][4*j] = z4;
                *(float4*)&sF[w][lane][4*j] = z4;
            }
        }
        __syncwarp();

        for (int p0 = 0; p0 < mr; p0 += 8) {
#pragma unroll
            for (int pp = 0; pp < 8; pp++) {
                const int p = p0 + pp;
                const float  yv = sY[w][p][cidx];
                const float4 fa = *(const float4*)&sF[w][p][fbase];
                const float4 fb = *(const float4*)&sF[w][p][fbase + 4];
                acc[0] += yv * fa.x;  acc[1] += yv * fa.y;
                acc[2] += yv * fa.z;  acc[3] += yv * fa.w;
                acc[4] += yv * fb.x;  acc[5] += yv * fb.y;
                acc[6] += yv * fb.z;  acc[7] += yv * fb.w;
            }
        }
        __syncwarp();
    }

    float4* o = (float4*)(out + (size_t)atom * 256 + lane * 8);
    o[0] = make_float4(acc[0], acc[1], acc[2], acc[3]);
    o[1] = make_float4(acc[4], acc[5], acc[6], acc[7]);
}

extern "C" void kernel_launch(void* const* d_in, const int* in_sizes, int n_in,
                              void* d_out, int out_size) {
    const float* pos       = (const float*)d_in[0];
    const float* W         = (const float*)d_in[1];
    const int*   centers   = (const int*)d_in[2];
    const int*   neighbors = (const int*)d_in[3];
    const int*   species   = (const int*)d_in[4];
    float*       out       = (float*)d_out;

    const int P      = in_sizes[2];
    const int nAtoms = in_sizes[4];

    k_fill<<<(P + 255) / 256, 256>>>(pos, centers, neighbors, species, P);
    k_acc<<<(nAtoms + 7) / 8, 256>>>(W, out, nAtoms);
}

// round 13
// speedup vs baseline: 1.4200x; 1.1404x over previous
#include <cuda_runtime.h>

// ---------------------------------------------------------------------------
// SphericalExpansion:
//  - k_fill filters r >= R_CUT pairs (fc==0 => exact zero contribution) and
//    stores (dx,dy,dz,species) payload per bucket slot.
//  - k_acc: TWO atoms per warp (lanes 0-15 -> atom A pairs, 16-31 -> atom B),
//    16-pair tiles, stride-20 smem rows (LDS.128), radial recurrence.
//    All 32 lanes accumulate both atoms' outputs. Self-resets g_count.
// ---------------------------------------------------------------------------

constexpr int MAX_ATOMS = 20000;
constexpr int CAP       = 96;       // mean filtered count ~16; huge margin
constexpr float R_CUT_F = 5.0f;

__device__ int    g_count[MAX_ATOMS];        // zero-initialized at module load
__device__ float4 g_vec[MAX_ATOMS * CAP];    // (dx,dy,dz, species-as-float)

__global__ void k_fill(const float* __restrict__ pos,
                       const int*   __restrict__ centers,
                       const int*   __restrict__ neighbors,
                       const int*   __restrict__ species, int P)
{
    int p = blockIdx.x * blockDim.x + threadIdx.x;
    if (p >= P) return;
    const int c  = centers[p];
    const int nb = neighbors[p];
    const float dx = __ldg(&pos[3 * nb + 0]) - __ldg(&pos[3 * c + 0]);
    const float dy = __ldg(&pos[3 * nb + 1]) - __ldg(&pos[3 * c + 1]);
    const float dz = __ldg(&pos[3 * nb + 2]) - __ldg(&pos[3 * c + 2]);
    const float r2 = dx * dx + dy * dy + dz * dz;
    if (r2 >= R_CUT_F * R_CUT_F) return;      // cosine cutoff -> exact zero
    const int slot = atomicAdd(&g_count[c], 1);
    if (slot < CAP) {
        const int s = __ldg(&species[nb]);
        g_vec[c * CAP + slot] = make_float4(dx, dy, dz, __int_as_float(s));
    }
}

__global__ __launch_bounds__(256) void k_acc(
    const float* __restrict__ W,     // [2,4] row-major
    float*       __restrict__ out,   // [nAtoms, 16, 16]
    int nAtoms)
{
    // stride 20 floats: 16B-aligned rows, conflict-free lane-major writes,
    // broadcast reads (all lanes of a warp read the same row p).
    __shared__ __align__(16) float sY[8][32][20];
    __shared__ __align__(16) float sF[8][32][20];
    __shared__ float sW[8];

    if (threadIdx.x < 8) sW[threadIdx.x] = W[threadIdx.x];
    __syncthreads();

    const int w    = threadIdx.x >> 5;
    const int lane = threadIdx.x & 31;

    const int atomA = blockIdx.x * 16 + w * 2;   // two atoms per warp
    const int atomB = atomA + 1;
    if (atomA >= nAtoms) return;
    const bool hasB = (atomB < nAtoms);

    int cntA = g_count[atomA];
    int cntB = hasB ? g_count[atomB] : 0;
    if (lane == 0) g_count[atomA] = 0;           // self-reset for next launch
    if (lane == 1 && hasB) g_count[atomB] = 0;
    if (cntA > CAP) cntA = CAP;
    if (cntB > CAP) cntB = CAP;

    const int  half   = lane >> 4;               // 0 -> A pairs, 1 -> B pairs
    const int  hl     = lane & 15;
    const int  myAtom = half ? atomB : atomA;
    const int  myCnt  = half ? cntB : cntA;

    float accA[8], accB[8];
#pragma unroll
    for (int j = 0; j < 8; j++) { accA[j] = 0.0f; accB[j] = 0.0f; }

    // lane owns out elements e = lane*8+j of EACH atom:
    //   comp = lane>>1 (const), col = (lane&1)*8+j
    const int cidx  = lane >> 1;
    const int fbase = (lane & 1) << 3;

    // Radial recurrence: rad_n = G * E^n * K1^(n^2)
    const float K1 = __expf(-0.6530612244897959f);   // exp(-(32/49))
    const float K2 = K1 * K1;

    const int tiles = max((cntA + 15) >> 4, (cntB + 15) >> 4);

    for (int t = 0; t < tiles; t++) {
        const int base = t << 4;
        int mA = cntA - base; mA = mA < 0 ? 0 : (mA > 16 ? 16 : mA);
        int mB = cntB - base; mB = mB < 0 ? 0 : (mB > 16 ? 16 : mB);
        const int mrA = (mA + 7) & ~7;
        const int mrB = (mB + 7) & ~7;

        const int k = base + hl;
        if (k < myCnt) {
            float Y[16], F[16];
            const float4 v = __ldg(&g_vec[myAtom * CAP + k]);
            const float r2   = v.x * v.x + v.y * v.y + v.z * v.z + 1e-12f;
            const float rinv = rsqrtf(r2);
            const float r    = r2 * rinv;
            const float x = v.x * rinv, y = v.y * rinv, z = v.z * rinv;
            const float x2 = x * x, y2 = y * y, z2 = z * z;

            Y[0]  = 0.28209479177387814f;
            Y[1]  = 0.4886025119029199f * y;
            Y[2]  = 0.4886025119029199f * z;
            Y[3]  = 0.4886025119029199f * x;
            Y[4]  = 1.0925484305920792f * x * y;
            Y[5]  = 1.0925484305920792f * y * z;
            Y[6]  = 0.31539156525252005f * (3.0f * z2 - 1.0f);
            Y[7]  = 1.0925484305920792f * x * z;
            Y[8]  = 0.5462742152960396f * (x2 - y2);
            Y[9]  = 0.5900435899266435f * y * (3.0f * x2 - y2);
            Y[10] = 2.890611442640554f  * x * y * z;
            Y[11] = 0.4570457994644658f * y * (5.0f * z2 - 1.0f);
            Y[12] = 0.3731763325901154f * z * (5.0f * z2 - 3.0f);
            Y[13] = 0.4570457994644658f * x * (5.0f * z2 - 1.0f);
            Y[14] = 1.445305721320277f  * z * (x2 - y2);
            Y[15] = 0.5900435899266435f * x * (x2 - 3.0f * y2);

            // r < R_CUT guaranteed by k_fill filter
            const float fc = 0.5f * (__cosf(0.6283185307179586f * r) + 1.0f);

            const int   s  = __float_as_int(v.w);
            const float b0 = fc * sW[s];
            const float b1 = fc * sW[4 + s];

            float rad = __expf(-1.28f * r * r);                  // G
            float u   = __expf(1.8285714285714286f * r) * K1;    // E*K1
#pragma unroll
            for (int n = 0; n < 8; n++) {
                F[n]     = b0 * rad;
                F[8 + n] = b1 * rad;
                rad *= u;
                u   *= K2;
            }

#pragma unroll
            for (int j = 0; j < 4; j++) {
                *(float4*)&sY[w][lane][4*j] = make_float4(Y[4*j], Y[4*j+1], Y[4*j+2], Y[4*j+3]);
                *(float4*)&sF[w][lane][4*j] = make_float4(F[4*j], F[4*j+1], F[4*j+2], F[4*j+3]);
            }
        } else if (hl < (half ? mrB : mrA)) {
            // pad rows the 8-unrolled accumulator reads: finite zeros
            const float4 z4 = make_float4(0.f, 0.f, 0.f, 0.f);
#pragma unroll
            for (int j = 0; j < 4; j++) {
                *(float4*)&sY[w][lane][4*j] = z4;
                *(float4*)&sF[w][lane][4*j] = z4;
            }
        }
        __syncwarp();

        // all 32 lanes accumulate atom A over rows [0, mrA)
        for (int p0 = 0; p0 < mrA; p0 += 8) {
#pragma unroll
            for (int pp = 0; pp < 8; pp++) {
                const int p = p0 + pp;
                const float  yv = sY[w][p][cidx];
                const float4 fa = *(const float4*)&sF[w][p][fbase];
                const float4 fb = *(const float4*)&sF[w][p][fbase + 4];
                accA[0] += yv * fa.x;  accA[1] += yv * fa.y;
                accA[2] += yv * fa.z;  accA[3] += yv * fa.w;
                accA[4] += yv * fb.x;  accA[5] += yv * fb.y;
                accA[6] += yv * fb.z;  accA[7] += yv * fb.w;
            }
        }
        // all 32 lanes accumulate atom B over rows [16, 16+mrB)
        for (int p0 = 0; p0 < mrB; p0 += 8) {
#pragma unroll
            for (int pp = 0; pp < 8; pp++) {
                const int p = 16 + p0 + pp;
                const float  yv = sY[w][p][cidx];
                const float4 fa = *(const float4*)&sF[w][p][fbase];
                const float4 fb = *(const float4*)&sF[w][p][fbase + 4];
                accB[0] += yv * fa.x;  accB[1] += yv * fa.y;
                accB[2] += yv * fa.z;  accB[3] += yv * fa.w;
                accB[4] += yv * fb.x;  accB[5] += yv * fb.y;
                accB[6] += yv * fb.z;  accB[7] += yv * fb.w;
            }
        }
        __syncwarp();
    }

    float4* oA = (float4*)(out + (size_t)atomA * 256 + lane * 8);
    oA[0] = make_float4(accA[0], accA[1], accA[2], accA[3]);
    oA[1] = make_float4(accA[4], accA[5], accA[6], accA[7]);
    if (hasB) {
        float4* oB = (float4*)(out + (size_t)atomB * 256 + lane * 8);
        oB[0] = make_float4(accB[0], accB[1], accB[2], accB[3]);
        oB[1] = make_float4(accB[4], accB[5], accB[6], accB[7]);
    }
}

extern "C" void kernel_launch(void* const* d_in, const int* in_sizes, int n_in,
                              void* d_out, int out_size) {
    const float* pos       = (const float*)d_in[0];
    const float* W         = (const float*)d_in[1];
    const int*   centers   = (const int*)d_in[2];
    const int*   neighbors = (const int*)d_in[3];
    const int*   species   = (const int*)d_in[4];
    float*       out       = (float*)d_out;

    const int P      = in_sizes[2];
    const int nAtoms = in_sizes[4];

    k_fill<<<(P + 255) / 256, 256>>>(pos, centers, neighbors, species, P);
    k_acc<<<(nAtoms + 15) / 16, 256>>>(W, out, nAtoms);
}